// round 4
// baseline (speedup 1.0000x reference)
#include <cuda_runtime.h>
#include <math.h>

// CTC loss forward. Alpha recurrence in scaled *double* precision (linear
// domain), with damped lag-2 global rescaling driven by an fp32 shadow copy.
// x (T,N,C) f32 log-softmax, y (N,S) i32, ilen (N) i32, tlen (N) i32.
// Output: scalar f32 = mean_n( -log_like_n / L_n ).

#define T_DIM 2048
#define N_DIM 64
#define C_DIM 256
#define S_DIM 256
#define NC    (N_DIM * C_DIM)

#define E_PAD   544          // padded extended-state count (E_max = 513)
#define NSTATE  544          // 17 warps of state threads
#define P_BASE  544          // 8 warps computing p-row
#define RED_BASE 800         // 1 reducer warp
#define NTHREADS 832         // 26 warps total

#define GAMMA 0.75f          // damping exponent for rescale feedback

__device__ float g_losses[N_DIM];

__global__ __launch_bounds__(NTHREADS, 1)
void ctc_fwd_kernel(const float* __restrict__ x,
                    const int*   __restrict__ y,
                    const int*   __restrict__ ilen,
                    const int*   __restrict__ tlen)
{
    __shared__ double A64[2][E_PAD];   // alpha (scaled linear, double)
    __shared__ float  A32[2][E_PAD];   // narrowed shadow for the reducer
    __shared__ double P[2][C_DIM];     // prob row (unscaled exp, as double)
    __shared__ int    ylab[S_DIM];
    __shared__ double invS[2];         // damped inverse scale, ping-pong
    __shared__ double cumlog_sh;

    const int n   = blockIdx.x;
    const int tid = threadIdx.x;
    const int Ti  = ilen[n];
    const int L   = tlen[n];
    const int Tend   = Ti - 1;        // last applied time step (freeze point)
    const int E_used = 2 * L + 1;

    const float* xb_n = x + n * C_DIM;   // + t*NC + c

    // ---------------- init ----------------
    if (tid < E_PAD) {
        A64[0][tid] = 0.0; A64[1][tid] = 0.0;
        A32[0][tid] = 0.f; A32[1][tid] = 0.f;
    }
    if (tid < S_DIM) ylab[tid] = y[n * S_DIM + tid];
    if (tid == 0) { invS[0] = 1.0; invS[1] = 1.0; }
    if (tid == 0) {
        double a0 = (double)__expf(xb_n[0]);               // alpha0[0] = p0[blank]
        A64[0][0] = a0; A32[0][0] = (float)a0;
    }
    if (tid == 1) {
        double a1 = (double)__expf(xb_n[y[n * S_DIM]]);    // alpha0[1] = p0[y0]
        A64[0][1] = a1; A32[0][1] = (float)a1;
    }

    // P threads: compute p_1 and prefetch rows 2..4 into registers
    float xa = 0.f, xbv = 0.f, xc = 0.f;
    const int c = tid - P_BASE;
    if (tid >= P_BASE && tid < RED_BASE) {
        P[1][c] = (double)__expf(xb_n[(size_t)1 * NC + c]);
        if (2 <= Tend) xa  = xb_n[(size_t)2 * NC + c];
        if (3 <= Tend) xbv = xb_n[(size_t)3 * NC + c];
        if (4 <= Tend) xc  = xb_n[(size_t)4 * NC + c];
    }

    __syncthreads();

    // state-thread per-state constants (need ylab)
    int  lbl  = 0;
    bool skip = false;
    bool active = false;
    if (tid < NSTATE) {
        const int s = tid;
        active = (s < E_used);
        if (s & 1) {
            const int k = (s - 1) >> 1;
            lbl = ylab[k];
            skip = (k > 0) && (lbl != 0) && (lbl != ylab[k - 1]);
        }
    }

    double cum = 0.0;                 // sum of applied gamma*log2(S)
    const int lane = tid & 31;

    // ---------------- main loop: t = 1 .. Tend ----------------
    for (int t = 1; t <= Tend; ++t) {
        const int cur = t & 1;
        const int prv = cur ^ 1;

        if (tid < NSTATE) {
            if (active) {
                const double m = P[cur][lbl] * invS[cur];  // off the add chain
                double v = A64[prv][tid];
                if (tid >= 1) v += A64[prv][tid - 1];
                if (skip)     v += A64[prv][tid - 2];
                const double r = v * m;
                A64[cur][tid] = r;
                A32[cur][tid] = (float)fmin(r, 1.0e30);    // safe narrowing
            }
        } else if (tid < RED_BASE) {
            // p for step t+1 (unscaled)
            if (t < Tend) {
                P[prv][c] = (double)__expf(xa);
            }
            xa = xbv; xbv = xc;
            const int r = t + 4;
            if (r <= Tend) xc = xb_n[(size_t)r * NC + c];
        } else {
            // reducer warp: S ~= sum(A_{t-1}); produce invS for step t+1
            float ss = 0.f;
            #pragma unroll
            for (int i = 0; i < 17; ++i) ss += A32[prv][lane + 32 * i];
            #pragma unroll
            for (int off = 16; off; off >>= 1)
                ss += __shfl_down_sync(0xffffffffu, ss, off);
            if (lane == 0 && t < Tend) {
                const float S  = fmaxf(ss, 1e-30f);
                const float lg = log2f(S);
                invS[prv] = (double)exp2f(-GAMMA * lg);   // consumed at t+1
                cum += (double)(GAMMA * lg);              // booked scale
            }
        }
        __syncthreads();
    }

    // ---------------- epilogue ----------------
    if (tid == RED_BASE) cumlog_sh = cum;
    __syncthreads();

    if (tid == 0) {
        const int bufT = Tend & 1;
        double v = A64[bufT][2 * L - 1] + A64[bufT][2 * L];
        v = fmax(v, 1e-300);
        const double LN2 = 0.69314718055994530942;
        // A = alpha * 2^{-cum}  =>  log alpha = log(A) + ln2 * cum
        const double ll = log(v) + LN2 * cumlog_sh;
        const int Ld = (L > 0) ? L : 1;
        g_losses[n] = (float)(-ll / (double)Ld);
    }
}

__global__ void ctc_reduce_kernel(float* __restrict__ out)
{
    if (blockIdx.x == 0 && threadIdx.x == 0) {
        float s = 0.f;
        #pragma unroll
        for (int i = 0; i < N_DIM; ++i) s += g_losses[i];   // fixed order
        out[0] = s / (float)N_DIM;
    }
}

extern "C" void kernel_launch(void* const* d_in, const int* in_sizes, int n_in,
                              void* d_out, int out_size)
{
    const float* x  = (const float*)d_in[0];
    const int*   y  = (const int*)  d_in[1];
    const int*   il = (const int*)  d_in[2];
    const int*   tl = (const int*)  d_in[3];
    float* out = (float*)d_out;

    ctc_fwd_kernel<<<N_DIM, NTHREADS>>>(x, y, il, tl);
    ctc_reduce_kernel<<<1, 32>>>(out);
}

// round 5
// speedup vs baseline: 2.7390x; 2.7390x over previous
#include <cuda_runtime.h>
#include <math.h>

// CTC loss forward, fp32 log2-domain lse3 recurrence.
// One CTA per batch element; 544 threads = one extended state each.
// x (T,N,C) f32 log-softmax, y (N,S) i32, ilen (N) i32, tlen (N) i32.
// Output: scalar f32 = mean_n( -log_like_n / L_n ).

#define T_DIM 2048
#define N_DIM 64
#define C_DIM 256
#define S_DIM 256
#define NC    (N_DIM * C_DIM)

#define NSTATE 544            // E_max = 513, padded to 17 warps
#define A_PAD  (NSTATE + 2)   // 2 leading pad cells (read as s-1, s-2)
#define NEGF   (-1.0e30f)
#define LOG2E_F 1.4426950408889634f

__device__ float g_losses[N_DIM];

__device__ __forceinline__ float ex2(float x) {
    float r; asm("ex2.approx.ftz.f32 %0, %1;" : "=f"(r) : "f"(x)); return r;
}
__device__ __forceinline__ float lg2(float x) {
    float r; asm("lg2.approx.f32 %0, %1;" : "=f"(r) : "f"(x)); return r;
}

__global__ __launch_bounds__(NSTATE, 1)
void ctc_fwd_kernel(const float* __restrict__ x,
                    const int*   __restrict__ y,
                    const int*   __restrict__ ilen,
                    const int*   __restrict__ tlen)
{
    __shared__ float A[2][A_PAD];      // alpha in log2 units, double-buffered

    const int n   = blockIdx.x;
    const int s   = threadIdx.x;
    const int Ti  = ilen[n];
    const int L   = tlen[n];
    const int Tend   = Ti - 1;         // last applied step (freeze point)
    const int E_used = 2 * L + 1;

    // ----- per-state constants -----
    int  lbl  = 0;
    bool skip = false;
    if (s & 1) {
        const int k = (s - 1) >> 1;
        lbl = y[n * S_DIM + k];
        skip = (k > 0) && (lbl != 0) && (lbl != y[n * S_DIM + k - 1]);
    }
    const bool active = (s < E_used);
    const float* gaddr = x + (size_t)n * C_DIM + lbl;   // + t*NC per step

    // ----- init -----
    A[0][s] = NEGF; A[1][s] = NEGF;                     // covers pads (s=0,1 slots)
    if (s >= A_PAD - 2) { A[0][s + 2] = NEGF; A[1][s + 2] = NEGF; }
    __syncthreads();
    if (s < 2 && s < E_used) A[0][s + 2] = LOG2E_F * gaddr[0];   // alpha0 = lp[0][s]
    // prefetch lp rows 1..4
    float v0 = 0.f, v1 = 0.f, v2 = 0.f, v3 = 0.f;
    if (1 <= Tend) v0 = __ldg(gaddr + (size_t)1 * NC);
    if (2 <= Tend) v1 = __ldg(gaddr + (size_t)2 * NC);
    if (3 <= Tend) v2 = __ldg(gaddr + (size_t)3 * NC);
    if (4 <= Tend) v3 = __ldg(gaddr + (size_t)4 * NC);
    __syncthreads();

    // ----- main loop, unrolled by 4 (t = 1, 5, 9, ...) -----
    #define STEP(CUR, PRV, LP)                                           \
    {                                                                    \
        const float a1 = A[PRV][s + 2];                                  \
        const float a2 = A[PRV][s + 1];                                  \
        const float a3 = skip ? A[PRV][s] : NEGF;                        \
        const float g  = fmaxf(a1, a2);                                  \
        const float sm = fminf(a1, a2);                                  \
        const float m  = fmaxf(g, a3);                                   \
        const float l2 = fminf(g, a3);                                   \
        const float e  = 1.0f + ex2(sm - m) + ex2(l2 - m);               \
        const float nv = m + lg2(e) + LOG2E_F * (LP);                    \
        if (active) A[CUR][s + 2] = nv;                                  \
    }

    for (int t = 1; t <= Tend; t += 4) {
        STEP(1, 0, v0);
        if (t + 4 <= Tend) v0 = __ldg(gaddr + (size_t)(t + 4) * NC);
        __syncthreads();
        if (t + 1 <= Tend) {
            STEP(0, 1, v1);
            if (t + 5 <= Tend) v1 = __ldg(gaddr + (size_t)(t + 5) * NC);
            __syncthreads();
        }
        if (t + 2 <= Tend) {
            STEP(1, 0, v2);
            if (t + 6 <= Tend) v2 = __ldg(gaddr + (size_t)(t + 6) * NC);
            __syncthreads();
        }
        if (t + 3 <= Tend) {
            STEP(0, 1, v3);
            if (t + 7 <= Tend) v3 = __ldg(gaddr + (size_t)(t + 7) * NC);
            __syncthreads();
        }
    }
    #undef STEP

    // ----- epilogue: logaddexp2 of the two terminal states -----
    if (s == 0) {
        const int b = Tend & 1;
        const float u1 = A[b][2 + 2 * L - 1];
        const float u2 = A[b][2 + 2 * L];
        const float m  = fmaxf(u1, u2);
        const float mn = fminf(u1, u2);
        const float ll2 = m + lg2(1.0f + ex2(mn - m));   // log2-likelihood
        const double LN2 = 0.69314718055994530942;
        const int Ld = (L > 0) ? L : 1;
        g_losses[n] = (float)(-((double)ll2 * LN2) / (double)Ld);
    }
}

__global__ void ctc_reduce_kernel(float* __restrict__ out)
{
    if (blockIdx.x == 0 && threadIdx.x == 0) {
        double acc = 0.0;
        #pragma unroll
        for (int i = 0; i < N_DIM; ++i) acc += (double)g_losses[i];  // fixed order
        out[0] = (float)(acc / (double)N_DIM);
    }
}

extern "C" void kernel_launch(void* const* d_in, const int* in_sizes, int n_in,
                              void* d_out, int out_size)
{
    const float* x  = (const float*)d_in[0];
    const int*   y  = (const int*)  d_in[1];
    const int*   il = (const int*)  d_in[2];
    const int*   tl = (const int*)  d_in[3];
    float* out = (float*)d_out;

    ctc_fwd_kernel<<<N_DIM, NSTATE>>>(x, y, il, tl);
    ctc_reduce_kernel<<<1, 32>>>(out);
}